// round 5
// baseline (speedup 1.0000x reference)
#include <cuda_runtime.h>

// LSTM recurrence (SLSTM reset='none') + Linear(128->1).
// B=1024, T=2048, IN=16, H=128.
//
// Persistent: 147 CTAs x 256 threads; CTA owns 7 batch rows for all T.
// Thread (kh = tid&1, j = tid>>1): computes ALL 4 gates of hidden unit j,
// for all 7 batch rows, over K-half kh (20 reg k's + 52 smem k's of 144).
// f32x2 packed FMAs (k-pairs in lanes). Bias pre-seeded in kh=0 accumulator.
// kh halves combined with ONE shfl.xor(1) per output; activations fully
// thread-local (kh0 owns batch rows 0-3, kh1 rows 4-6). One barrier/step.
// NT=256 -> 255 regs/thread: ~100 free regs for deep LDS pipelining.

#define T_    2048
#define IN_   16
#define KREG  40                    // k's in registers (20 per kh half)
#define NT    256
#define NCTA  147
#define BB    7
#define BTOT  1024
#define HXROW 144
#define HXBUF (BB * HXROW)               // 1008 floats
#define WSM_U64 (26 * 128 * 2 * 4)       // 26624 u64 (104 k x 512 gate-rows)
#define WSM_FLOATS (WSM_U64 * 2)         // 53248
#define SMEM_FLOATS (WSM_FLOATS + 2 * HXBUF + 128)   // 55392
#define SMEM_BYTES  (SMEM_FLOATS * 4)                // 221568

typedef unsigned long long u64;

__device__ __forceinline__ void ffma2(u64 &d, u64 a, u64 b) {
    asm("fma.rn.f32x2 %0, %1, %2, %0;" : "+l"(d) : "l"(a), "l"(b));
}
__device__ __forceinline__ float2 unpk(u64 v) {
    float2 r;
    asm("mov.b64 {%0, %1}, %2;" : "=f"(r.x), "=f"(r.y) : "l"(v));
    return r;
}
__device__ __forceinline__ u64 pack2(float lo, float hi) {
    u64 v;
    asm("mov.b64 %0, {%1, %2};" : "=l"(v) : "f"(lo), "f"(hi));
    return v;
}
__device__ __forceinline__ float ex2a(float x) {
    float y; asm("ex2.approx.f32 %0, %1;" : "=f"(y) : "f"(x)); return y;
}
__device__ __forceinline__ float rcpa(float x) {
    float y; asm("rcp.approx.f32 %0, %1;" : "=f"(y) : "f"(x)); return y;
}
__device__ __forceinline__ float sig_(float x) {
    return rcpa(1.0f + ex2a(-1.4426950408889634f * x));
}
__device__ __forceinline__ float tanh_(float x) {
    return 2.0f * rcpa(1.0f + ex2a(-2.8853900817779268f * x)) - 1.0f;
}

extern "C" __global__ void __launch_bounds__(NT, 1)
slstm_kernel(const float* __restrict__ x, const float* __restrict__ W_ih,
             const float* __restrict__ W_hh, const float* __restrict__ b_ih,
             const float* __restrict__ b_hh, const float* __restrict__ fc_w,
             const float* __restrict__ fc_b, float* __restrict__ out)
{
    extern __shared__ float sm[];
    float* Wsm = sm;                          // 104 k x 512 gate-rows, pairs
    float* hx  = sm + WSM_FLOATS;             // 2 x [7][144]
    float* fcw = sm + WSM_FLOATS + 2 * HXBUF;

    const int tid = threadIdx.x;
    const int kh  = tid & 1;                  // K half
    const int j   = tid >> 1;                 // hidden unit 0..127
    const int bbase = blockIdx.x * BB;

    // ---- prologue: SMEM weights for k = KREG..143 ----
    // u64 index = ((kp*128 + jj)*2 + khs)*4 + g ;  k0 = KREG + khs*52 + 2*kp
    for (int s = tid; s < WSM_U64; s += NT) {
        const int g   = s & 3;
        const int khs = (s >> 2) & 1;
        const int jj  = (s >> 3) & 127;
        const int kp  = s >> 10;              // 0..25
        const int k0  = KREG + khs * 52 + 2 * kp;
        const int row = g * 128 + jj;
        float w0, w1;
        if (k0 < 128) {
            w0 = W_hh[row * 128 + k0];
            w1 = W_hh[row * 128 + k0 + 1];
        } else {
            w0 = W_ih[row * 16 + (k0 - 128)];
            w1 = W_ih[row * 16 + (k0 - 127)];
        }
        Wsm[2 * s]     = w0;
        Wsm[2 * s + 1] = w1;
    }
    if (tid < 128) fcw[tid] = fc_w[tid];

    // ---- register weights: k = kh*20 .. kh*20+19 (10 pairs x 4 gates) ----
    u64 wr[4][10];
#pragma unroll
    for (int g = 0; g < 4; ++g) {
        const int row = g * 128 + j;
#pragma unroll
        for (int i = 0; i < 10; ++i)
            wr[g][i] = *(const u64*)&W_hh[row * 128 + kh * 20 + 2 * i];
    }

    // biases (seeded into kh=0 accumulators each step)
    u64 bgp[4];
#pragma unroll
    for (int g = 0; g < 4; ++g) {
        const float bv = b_ih[g * 128 + j] + b_hh[g * 128 + j];
        bgp[g] = kh ? 0ull : pack2(bv, 0.0f);
    }

    // ---- init: h0 = 0, x(0) staged ----
    for (int s = tid; s < BB * 128; s += NT) {
        const int b = s / 128, k = s & 127;
        hx[b * HXROW + k] = 0.0f;
    }
    {
        const int b = tid >> 4, i = tid & 15;
        if (tid < BB * IN_)
            hx[b * HXROW + 128 + i] =
                (bbase + b < BTOT) ? x[(bbase + b) * (T_ * IN_) + i] : 0.0f;
    }
    float c[4] = {0.0f, 0.0f, 0.0f, 0.0f};    // rows kh*4 .. (kh0:4, kh1:3)
    __syncthreads();

    const int khr = kh * 20;           // reg-section h offset (floats)
    const int khs = KREG + kh * 52;    // smem-section h offset (floats)
    const u64* Wu = (const u64*)Wsm;
    const int wb  = (j * 2 + kh) * 4;  // thread's weight base within kp (u64)
    const int npp = 4 - kh;            // #batch rows this thread activates
    const int xb = tid >> 4, xi = tid & 15;
    const bool xok = (tid < BB * IN_) && (bbase + xb < BTOT);

    int cur = 0;
    for (int t = 0; t < T_; ++t) {
        // prefetch x(t+1)
        float xv = 0.0f;
        const bool doX = xok && (t + 1 < T_);
        if (doX)
            xv = x[(bbase + xb) * (T_ * IN_) + (t + 1) * IN_ + xi];

        const float* hb = hx + cur * HXBUF;

        u64 acc[4][BB];
#pragma unroll
        for (int g = 0; g < 4; ++g) {
#pragma unroll
            for (int p = 0; p < BB; ++p) acc[g][p] = (p == 0) ? bgp[g] : 0ull;
        }

        // -------- register-weight section: 5 float4 chunks (20 k's) --------
#pragma unroll
        for (int cc = 0; cc < 5; ++cc) {
#pragma unroll
            for (int p = 0; p < BB; ++p) {
                const ulonglong2 hv =
                    *(const ulonglong2*)&hb[p * HXROW + khr + 4 * cc];
#pragma unroll
                for (int g = 0; g < 4; ++g) {
                    ffma2(acc[g][p], wr[g][2 * cc],     hv.x);
                    ffma2(acc[g][p], wr[g][2 * cc + 1], hv.y);
                }
            }
        }

        // -------- smem-weight section: 13 float4 chunks (52 k's) --------
#pragma unroll
        for (int cc = 0; cc < 13; ++cc) {
            const u64* wp = Wu + wb + (2 * cc) * 1024;
            const ulonglong2 wA = *(const ulonglong2*)(wp);          // pair0 g0,g1
            const ulonglong2 wB = *(const ulonglong2*)(wp + 2);      // pair0 g2,g3
            const ulonglong2 wC = *(const ulonglong2*)(wp + 1024);   // pair1 g0,g1
            const ulonglong2 wD = *(const ulonglong2*)(wp + 1026);   // pair1 g2,g3
#pragma unroll
            for (int p = 0; p < BB; ++p) {
                const ulonglong2 hv =
                    *(const ulonglong2*)&hb[p * HXROW + khs + 4 * cc];
                ffma2(acc[0][p], wA.x, hv.x);
                ffma2(acc[1][p], wA.y, hv.x);
                ffma2(acc[2][p], wB.x, hv.x);
                ffma2(acc[3][p], wB.y, hv.x);
                ffma2(acc[0][p], wC.x, hv.y);
                ffma2(acc[1][p], wC.y, hv.y);
                ffma2(acc[2][p], wD.x, hv.y);
                ffma2(acc[3][p], wD.y, hv.y);
            }
        }

        // -------- reduce: lane-sum, then ONE shfl.xor(1) per output --------
        // Thread sends its partials for the PARTNER's rows; receives partner's
        // partials for its OWN rows. own row p_own = kh*4+i ; sent row = (kh^1)*4+i.
        float gate[4][4];
#pragma unroll
        for (int g = 0; g < 4; ++g) {
#pragma unroll
            for (int i = 0; i < 4; ++i) {
                const int p_snd = (kh ^ 1) * 4 + i;     // partner's row
                const int p_own = kh * 4 + i;           // my row
                const float2 sv = unpk(acc[g][p_snd < BB ? p_snd : 0]);
                const float2 ov = (p_own < BB) ? unpk(acc[g][p_own])
                                               : make_float2(0.f, 0.f);
                const float snd = sv.x + sv.y;
                const float own = ov.x + ov.y;
                gate[g][i] = own + __shfl_xor_sync(0xffffffffu, snd, 1);
            }
        }

        // -------- activations: thread-local, rows kh*4 .. kh*4+npp-1 --------
        float* hn = hx + (cur ^ 1) * HXBUF;
#pragma unroll
        for (int i = 0; i < 4; ++i) {
            if (i < npp) {
                const int p = kh * 4 + i;
                const float ig = sig_(gate[0][i]);
                const float fg = sig_(gate[1][i]);
                const float gg = tanh_(gate[2][i]);
                const float og = sig_(gate[3][i]);
                const float cn = fg * c[i] + ig * gg;
                c[i] = cn;
                hn[p * HXROW + j] = og * tanh_(cn);
            }
        }
        if (doX)
            hn[xb * HXROW + 128 + xi] = xv;

        __syncthreads();
        cur ^= 1;
    }

    // ---- output: out[b] = h_T[b] . fc_w + fc_b ----
    if (tid < BB && bbase + tid < BTOT) {
        const float* hbf = hx + cur * HXBUF + tid * HXROW;
        float s = fc_b[0];
#pragma unroll 8
        for (int k = 0; k < 128; ++k) s += hbf[k] * fcw[k];
        out[bbase + tid] = s;
    }
}

extern "C" void kernel_launch(void* const* d_in, const int* in_sizes, int n_in,
                              void* d_out, int out_size)
{
    const float* x    = (const float*)d_in[0];
    const float* W_ih = (const float*)d_in[1];
    const float* W_hh = (const float*)d_in[2];
    const float* b_ih = (const float*)d_in[3];
    const float* b_hh = (const float*)d_in[4];
    const float* fc_w = (const float*)d_in[5];
    const float* fc_b = (const float*)d_in[6];
    float* out = (float*)d_out;

    cudaFuncSetAttribute(slstm_kernel,
                         cudaFuncAttributeMaxDynamicSharedMemorySize, SMEM_BYTES);
    slstm_kernel<<<NCTA, NT, SMEM_BYTES>>>(x, W_ih, W_hh, b_ih, b_hh,
                                           fc_w, fc_b, out);
}

// round 7
// speedup vs baseline: 1.0169x; 1.0169x over previous
#include <cuda_runtime.h>

// LSTM recurrence (SLSTM reset='none') + Linear(128->1).
// B=1024, T=2048, IN=16, H=128.
//
// Persistent: 147 CTAs x 512 threads; CTA owns 7 batch rows for all T.
// Thread (q = tid&3, j = tid>>2): computes ALL 4 gates of hidden unit j,
// for all 7 batch rows, over K-quarter q (36 of 144 k's: 12 in regs,
// 24 in smem), in two gate-pair passes (i,f then g,o) to cap accumulator
// register pressure at 28. f32x2 packed FMAs (k-pairs in lanes).
// Weights read ONCE per SM per step; weight LDS.128 made phase-conflict-free
// by XOR-ing the gate-pair slot with (j&1). Reduce across the 4 q-threads
// with 24 shfl/step (2-level xor, parity-kept rows); thread q owns rows
// {q, q+4} (q<3). One __syncthreads per step.
//
// R7 fix vs R6: smem-section h offset is 12 + 4*m (2 k-pairs = 4 floats per
// iteration), not 12 + 8*m. R6's stride-8 read misaligned weights vs h.

#define T_    2048
#define IN_   16
#define NT    512
#define NCTA  147
#define BB    7
#define BTOT  1024
#define HXROW 144
#define HXBUF (BB * HXROW)                 // 1008 floats
#define WSM_U64 (12 * 2048)                // 24576 u64 = 196608 B
#define SMEM_FLOATS (WSM_U64 * 2 + 2 * HXBUF + 128)   // 51296
#define SMEM_BYTES  (SMEM_FLOATS * 4)                  // 205184

typedef unsigned long long u64;

__device__ __forceinline__ void ffma2(u64 &d, u64 a, u64 b) {
    asm("fma.rn.f32x2 %0, %1, %2, %0;" : "+l"(d) : "l"(a), "l"(b));
}
__device__ __forceinline__ float2 unpk(u64 v) {
    float2 r;
    asm("mov.b64 {%0, %1}, %2;" : "=f"(r.x), "=f"(r.y) : "l"(v));
    return r;
}
__device__ __forceinline__ float ex2a(float x) {
    float y; asm("ex2.approx.f32 %0, %1;" : "=f"(y) : "f"(x)); return y;
}
__device__ __forceinline__ float rcpa(float x) {
    float y; asm("rcp.approx.f32 %0, %1;" : "=f"(y) : "f"(x)); return y;
}
__device__ __forceinline__ float sig_(float x) {
    return rcpa(1.0f + ex2a(-1.4426950408889634f * x));
}
__device__ __forceinline__ float tanh_(float x) {
    return 2.0f * rcpa(1.0f + ex2a(-2.8853900817779268f * x)) - 1.0f;
}

extern "C" __global__ void __launch_bounds__(NT, 1)
slstm_kernel(const float* __restrict__ x, const float* __restrict__ W_ih,
             const float* __restrict__ W_hh, const float* __restrict__ b_ih,
             const float* __restrict__ b_hh, const float* __restrict__ fc_w,
             const float* __restrict__ fc_b, float* __restrict__ out)
{
    extern __shared__ float sm[];
    float* Wsm = sm;                          // 12 pl x [j][q][half][gg] u64
    float* hx  = sm + WSM_U64 * 2;            // 2 x [7][144]
    float* fcw = sm + WSM_U64 * 2 + 2 * HXBUF;

    const int tid = threadIdx.x;
    const int q   = tid & 3;                  // K quarter
    const int j   = tid >> 2;                 // hidden unit 0..127
    const int kb  = q & 1;
    const int kt  = (q >> 1) & 1;
    const int bbase = blockIdx.x * BB;

    // ---- prologue: SMEM weights (smem pairs 6..17 of each quarter) ----
    // u64 idx s = pl*2048 + j*16 + q*4 + half*2 + gg, half = gp ^ (j&1),
    // gate g = 2*gp + gg, pair: k0 = q*36 + 12 + 2*pl.
    for (int s = tid; s < WSM_U64; s += NT) {
        const int gg   = s & 1;
        const int half = (s >> 1) & 1;
        const int qq   = (s >> 2) & 3;
        const int jj   = (s >> 4) & 127;
        const int pl   = s >> 11;
        const int gp   = half ^ (jj & 1);
        const int g    = 2 * gp + gg;
        const int k0   = qq * 36 + 12 + 2 * pl;
        const int row  = g * 128 + jj;
        float w0, w1;
        if (k0 < 128) {
            w0 = W_hh[row * 128 + k0];
            w1 = W_hh[row * 128 + k0 + 1];
        } else {
            w0 = W_ih[row * 16 + (k0 - 128)];
            w1 = W_ih[row * 16 + (k0 - 127)];
        }
        Wsm[2 * s]     = w0;
        Wsm[2 * s + 1] = w1;
    }
    if (tid < 128) fcw[tid] = fc_w[tid];

    // ---- register weights: pairs 0..5 of this quarter, all 4 gates ----
    u64 wr[4][6];
#pragma unroll
    for (int g = 0; g < 4; ++g) {
        const int row = g * 128 + j;
#pragma unroll
        for (int i = 0; i < 6; ++i)
            wr[g][i] = *(const u64*)&W_hh[row * 128 + q * 36 + 2 * i];
    }
    float bias[4];
#pragma unroll
    for (int g = 0; g < 4; ++g)
        bias[g] = b_ih[g * 128 + j] + b_hh[g * 128 + j];

    // ---- init: h0 = 0, x(0) staged ----
    for (int s = tid; s < BB * 128; s += NT) {
        const int b = s >> 7, k = s & 127;
        hx[b * HXROW + k] = 0.0f;
    }
    {
        const int b = tid >> 4, i = tid & 15;
        if (tid < BB * IN_)
            hx[b * HXROW + 128 + i] =
                (bbase + b < BTOT) ? x[(bbase + b) * (T_ * IN_) + i] : 0.0f;
    }
    float c0 = 0.0f, c1 = 0.0f;               // rows q and q+4 (q<3)
    __syncthreads();

    const u64* Wu = (const u64*)Wsm;
    const int xb = tid >> 4, xi = tid & 15;
    const bool xok = (tid < BB * IN_) && (bbase + xb < BTOT);
    const int jq = j * 16 + q * 4;            // weight addr component

    int cur = 0;
    for (int t = 0; t < T_; ++t) {
        float xv = 0.0f;
        const bool doX = xok && (t + 1 < T_);
        if (doX)
            xv = x[(bbase + xb) * (T_ * IN_) + (t + 1) * IN_ + xi];

        const float* hb = hx + cur * HXBUF + q * 36;  // quarter base folded in

        float gv[4][2];                       // [gate][row-slot] final gates

#pragma unroll
        for (int gp = 0; gp < 2; ++gp) {
            const int gA = 2 * gp, gB = 2 * gp + 1;
            u64 accA[7], accB[7];
#pragma unroll
            for (int p = 0; p < 7; ++p) { accA[p] = 0ull; accB[p] = 0ull; }

            // ---- register-weight section: 3 x 16B chunks (6 pairs) ----
#pragma unroll
            for (int cc = 0; cc < 3; ++cc) {
#pragma unroll
                for (int p = 0; p < 7; ++p) {
                    const ulonglong2 hv =
                        *(const ulonglong2*)&hb[p * HXROW + 4 * cc];
                    ffma2(accA[p], wr[gA][2 * cc],     hv.x);
                    ffma2(accB[p], wr[gB][2 * cc],     hv.x);
                    ffma2(accA[p], wr[gA][2 * cc + 1], hv.y);
                    ffma2(accB[p], wr[gB][2 * cc + 1], hv.y);
                }
            }

            // ---- smem-weight section: 6 iters x 2 pairs (12 pairs) ----
            const int hoff = gp ^ (j & 1);    // conflict-free gate-pair slot
#pragma unroll
            for (int m = 0; m < 6; ++m) {
                const ulonglong2 w0 = *(const ulonglong2*)
                    (Wu + (2 * m) * 2048 + jq + hoff * 2);
                const ulonglong2 w1 = *(const ulonglong2*)
                    (Wu + (2 * m + 1) * 2048 + jq + hoff * 2);
#pragma unroll
                for (int p = 0; p < 7; ++p) {
                    const ulonglong2 hv =
                        *(const ulonglong2*)&hb[p * HXROW + 12 + 4 * m];
                    ffma2(accA[p], w0.x, hv.x);
                    ffma2(accB[p], w0.y, hv.x);
                    ffma2(accA[p], w1.x, hv.y);
                    ffma2(accB[p], w1.y, hv.y);
                }
            }

            // ---- reduce across q-threads ----
            float sA[7], sB[7];
#pragma unroll
            for (int p = 0; p < 7; ++p) {
                const float2 a = unpk(accA[p]); sA[p] = a.x + a.y;
                const float2 b = unpk(accB[p]); sB[p] = b.x + b.y;
            }
            // level 1 (xor 1): keep rows with (p&1)==kb
#pragma unroll
            for (int sl = 0; sl < 4; ++sl) {
                const float payA = kb ? sA[2 * sl]
                                      : sA[(2 * sl + 1 > 6) ? 6 : 2 * sl + 1];
                const float rcA = __shfl_xor_sync(0xffffffffu, payA, 1);
                sA[2 * sl] += kb ? 0.0f : rcA;
                if (sl < 3) sA[2 * sl + 1] += kb ? rcA : 0.0f;
                const float payB = kb ? sB[2 * sl]
                                      : sB[(2 * sl + 1 > 6) ? 6 : 2 * sl + 1];
                const float rcB = __shfl_xor_sync(0xffffffffu, payB, 1);
                sB[2 * sl] += kb ? 0.0f : rcB;
                if (sl < 3) sB[2 * sl + 1] += kb ? rcB : 0.0f;
            }
            // level 2 (xor 2): my rows {q, q+4}, partner rows {q^2, (q^2)+4}
            {
                const float vm0A = kt ? (kb ? sA[3] : sA[2]) : (kb ? sA[1] : sA[0]);
                const float vm1A = kt ? (kb ? sA[0] : sA[6]) : (kb ? sA[5] : sA[4]);
                const float vp0A = kt ? (kb ? sA[1] : sA[0]) : (kb ? sA[3] : sA[2]);
                const float vp1A = kt ? (kb ? sA[5] : sA[4]) : (kb ? sA[0] : sA[6]);
                gv[gA][0] = vm0A + __shfl_xor_sync(0xffffffffu, vp0A, 2) + bias[gA];
                gv[gA][1] = vm1A + __shfl_xor_sync(0xffffffffu, vp1A, 2) + bias[gA];
                const float vm0B = kt ? (kb ? sB[3] : sB[2]) : (kb ? sB[1] : sB[0]);
                const float vm1B = kt ? (kb ? sB[0] : sB[6]) : (kb ? sB[5] : sB[4]);
                const float vp0B = kt ? (kb ? sB[1] : sB[0]) : (kb ? sB[3] : sB[2]);
                const float vp1B = kt ? (kb ? sB[5] : sB[4]) : (kb ? sB[0] : sB[6]);
                gv[gB][0] = vm0B + __shfl_xor_sync(0xffffffffu, vp0B, 2) + bias[gB];
                gv[gB][1] = vm1B + __shfl_xor_sync(0xffffffffu, vp1B, 2) + bias[gB];
            }
        }

        // ---- activations: rows q and q+4 (q<3) ----
        float* hn = hx + (cur ^ 1) * HXBUF;
        {
            const float cn = sig_(gv[1][0]) * c0 + sig_(gv[0][0]) * tanh_(gv[2][0]);
            c0 = cn;
            hn[q * HXROW + j] = sig_(gv[3][0]) * tanh_(cn);
        }
        {
            const float cn = sig_(gv[1][1]) * c1 + sig_(gv[0][1]) * tanh_(gv[2][1]);
            const float hv = sig_(gv[3][1]) * tanh_(cn);
            if (q < 3) {
                c1 = cn;
                hn[(q + 4) * HXROW + j] = hv;
            }
        }
        if (doX)
            hn[xb * HXROW + 128 + xi] = xv;

        __syncthreads();
        cur ^= 1;
    }

    // ---- output: out[b] = h_T[b] . fc_w + fc_b ----
    if (tid < BB && bbase + tid < BTOT) {
        const float* hbf = hx + cur * HXBUF + tid * HXROW;
        float s = fc_b[0];
#pragma unroll 8
        for (int k = 0; k < 128; ++k) s += hbf[k] * fcw[k];
        out[bbase + tid] = s;
    }
}

extern "C" void kernel_launch(void* const* d_in, const int* in_sizes, int n_in,
                              void* d_out, int out_size)
{
    const float* x    = (const float*)d_in[0];
    const float* W_ih = (const float*)d_in[1];
    const float* W_hh = (const float*)d_in[2];
    const float* b_ih = (const float*)d_in[3];
    const float* b_hh = (const float*)d_in[4];
    const float* fc_w = (const float*)d_in[5];
    const float* fc_b = (const float*)d_in[6];
    float* out = (float*)d_out;

    cudaFuncSetAttribute(slstm_kernel,
                         cudaFuncAttributeMaxDynamicSharedMemorySize, SMEM_BYTES);
    slstm_kernel<<<NCTA, NT, SMEM_BYTES>>>(x, W_ih, W_hh, b_ih, b_hh,
                                           fc_w, fc_b, out);
}

// round 8
// speedup vs baseline: 1.1375x; 1.1186x over previous
#include <cuda_runtime.h>

// LSTM recurrence (SLSTM reset='none') + Linear(128->1).
// B=1024, T=2048, IN=16, H=128.
//
// Persistent: 147 CTAs x 512 threads; CTA owns 7 batch rows for all T.
// Thread (q = tid&3, j = tid>>2): ALL 4 gates of hidden unit j over
// K-quarter q (36 of 144 k's: 12 in regs, 24 in smem), in two ROW passes
// (rows 0-3, then rows 4-6) so each h chunk is loaded ONCE (63 h-LDS vs
// 126 in the gate-pass split) while acc pressure stays <= 32 regs.
// Weights re-read once per pass (2x/step) -- crossbar still under the FMA
// floor. f32x2 packed FMAs. (j&1) swizzle keeps both gate-pair weight
// LDS.128 conflict-free per 8-lane phase. Per-pass 2-level parity shuffle
// reduce (12 shfl/pass); thread q owns rows q (pass 1) and q+4 (pass 2,
// q<3). One __syncthreads per step.

#define T_    2048
#define IN_   16
#define NT    512
#define NCTA  147
#define BB    7
#define BTOT  1024
#define HXROW 144
#define HXBUF (BB * HXROW)                 // 1008 floats
#define WSM_U64 (12 * 2048)                // 24576 u64 = 196608 B
#define SMEM_FLOATS (WSM_U64 * 2 + 2 * HXBUF + 128)   // 51296
#define SMEM_BYTES  (SMEM_FLOATS * 4)                  // 205184

typedef unsigned long long u64;

__device__ __forceinline__ void ffma2(u64 &d, u64 a, u64 b) {
    asm("fma.rn.f32x2 %0, %1, %2, %0;" : "+l"(d) : "l"(a), "l"(b));
}
__device__ __forceinline__ float2 unpk(u64 v) {
    float2 r;
    asm("mov.b64 {%0, %1}, %2;" : "=f"(r.x), "=f"(r.y) : "l"(v));
    return r;
}
__device__ __forceinline__ float ex2a(float x) {
    float y; asm("ex2.approx.f32 %0, %1;" : "=f"(y) : "f"(x)); return y;
}
__device__ __forceinline__ float rcpa(float x) {
    float y; asm("rcp.approx.f32 %0, %1;" : "=f"(y) : "f"(x)); return y;
}
__device__ __forceinline__ float sig_(float x) {
    return rcpa(1.0f + ex2a(-1.4426950408889634f * x));
}
__device__ __forceinline__ float tanh_(float x) {
    return 2.0f * rcpa(1.0f + ex2a(-2.8853900817779268f * x)) - 1.0f;
}

extern "C" __global__ void __launch_bounds__(NT, 1)
slstm_kernel(const float* __restrict__ x, const float* __restrict__ W_ih,
             const float* __restrict__ W_hh, const float* __restrict__ b_ih,
             const float* __restrict__ b_hh, const float* __restrict__ fc_w,
             const float* __restrict__ fc_b, float* __restrict__ out)
{
    extern __shared__ float sm[];
    float* Wsm = sm;                          // 12 pl x [j][q][half][gg] u64
    float* hx  = sm + WSM_U64 * 2;            // 2 x [7][144]
    float* fcw = sm + WSM_U64 * 2 + 2 * HXBUF;

    const int tid = threadIdx.x;
    const int q   = tid & 3;                  // K quarter
    const int j   = tid >> 2;                 // hidden unit 0..127
    const int kb  = q & 1;
    const int kt  = (q >> 1) & 1;
    const int bbase = blockIdx.x * BB;

    // ---- prologue: SMEM weights (smem pairs 6..17 of each quarter) ----
    // u64 idx s = pl*2048 + j*16 + q*4 + half*2 + gg, half = gp ^ (j&1),
    // gate g = 2*gp + gg, pair: k0 = q*36 + 12 + 2*pl.  (verified in R7)
    for (int s = tid; s < WSM_U64; s += NT) {
        const int gg   = s & 1;
        const int half = (s >> 1) & 1;
        const int qq   = (s >> 2) & 3;
        const int jj   = (s >> 4) & 127;
        const int pl   = s >> 11;
        const int gp   = half ^ (jj & 1);
        const int g    = 2 * gp + gg;
        const int k0   = qq * 36 + 12 + 2 * pl;
        const int row  = g * 128 + jj;
        float w0, w1;
        if (k0 < 128) {
            w0 = W_hh[row * 128 + k0];
            w1 = W_hh[row * 128 + k0 + 1];
        } else {
            w0 = W_ih[row * 16 + (k0 - 128)];
            w1 = W_ih[row * 16 + (k0 - 127)];
        }
        Wsm[2 * s]     = w0;
        Wsm[2 * s + 1] = w1;
    }
    if (tid < 128) fcw[tid] = fc_w[tid];

    // ---- register weights: pairs 0..5 of this quarter, all 4 gates ----
    u64 wr[4][6];
#pragma unroll
    for (int g = 0; g < 4; ++g) {
        const int row = g * 128 + j;
#pragma unroll
        for (int i = 0; i < 6; ++i)
            wr[g][i] = *(const u64*)&W_hh[row * 128 + q * 36 + 2 * i];
    }
    float bias[4];
#pragma unroll
    for (int g = 0; g < 4; ++g)
        bias[g] = b_ih[g * 128 + j] + b_hh[g * 128 + j];

    // ---- init: h0 = 0, x(0) staged ----
    for (int s = tid; s < BB * 128; s += NT) {
        const int b = s >> 7, k = s & 127;
        hx[b * HXROW + k] = 0.0f;
    }
    {
        const int b = tid >> 4, i = tid & 15;
        if (tid < BB * IN_)
            hx[b * HXROW + 128 + i] =
                (bbase + b < BTOT) ? x[(bbase + b) * (T_ * IN_) + i] : 0.0f;
    }
    float c0 = 0.0f, c1 = 0.0f;               // rows q and q+4 (q<3)
    __syncthreads();

    const u64* Wu = (const u64*)Wsm;
    const int xb = tid >> 4, xi = tid & 15;
    const bool xok = (tid < BB * IN_) && (bbase + xb < BTOT);
    const int wbase = j * 16 + q * 4;                 // weight addr component
    const int h0off = ( (j & 1)      ) << 1;          // gp0 (gates 0,1) slot
    const int h1off = ( (j & 1) ^ 1  ) << 1;          // gp1 (gates 2,3) slot

    int cur = 0;
    for (int t = 0; t < T_; ++t) {
        float xv = 0.0f;
        const bool doX = xok && (t + 1 < T_);
        if (doX)
            xv = x[(bbase + xb) * (T_ * IN_) + (t + 1) * IN_ + xi];

        const float* hb = hx + cur * HXBUF + q * 36;  // quarter base folded in
        float* hn = hx + (cur ^ 1) * HXBUF;

        // ================= PASS 1: rows 0..3 =================
        {
            u64 acc[4][4];
#pragma unroll
            for (int g = 0; g < 4; ++g)
#pragma unroll
                for (int r = 0; r < 4; ++r) acc[g][r] = 0ull;

            // reg-weight section: 3 chunks (6 pairs)
#pragma unroll
            for (int cc = 0; cc < 3; ++cc) {
#pragma unroll
                for (int r = 0; r < 4; ++r) {
                    const ulonglong2 hv =
                        *(const ulonglong2*)&hb[r * HXROW + 4 * cc];
#pragma unroll
                    for (int g = 0; g < 4; ++g) {
                        ffma2(acc[g][r], wr[g][2 * cc],     hv.x);
                        ffma2(acc[g][r], wr[g][2 * cc + 1], hv.y);
                    }
                }
            }
            // smem-weight section: 6 iters x 2 pairs
#pragma unroll
            for (int m = 0; m < 6; ++m) {
                const u64* bp = Wu + (2 * m) * 2048 + wbase;
                const ulonglong2 w0A = *(const ulonglong2*)(bp + h0off);
                const ulonglong2 w0B = *(const ulonglong2*)(bp + h1off);
                const ulonglong2 w1A = *(const ulonglong2*)(bp + 2048 + h0off);
                const ulonglong2 w1B = *(const ulonglong2*)(bp + 2048 + h1off);
#pragma unroll
                for (int r = 0; r < 4; ++r) {
                    const ulonglong2 hv =
                        *(const ulonglong2*)&hb[r * HXROW + 12 + 4 * m];
                    ffma2(acc[0][r], w0A.x, hv.x);
                    ffma2(acc[1][r], w0A.y, hv.x);
                    ffma2(acc[2][r], w0B.x, hv.x);
                    ffma2(acc[3][r], w0B.y, hv.x);
                    ffma2(acc[0][r], w1A.x, hv.y);
                    ffma2(acc[1][r], w1A.y, hv.y);
                    ffma2(acc[2][r], w1B.x, hv.y);
                    ffma2(acc[3][r], w1B.y, hv.y);
                }
            }

            // reduce (rows 0..3) -> thread q owns row q
            float gv[4];
#pragma unroll
            for (int g = 0; g < 4; ++g) {
                float s0_, s1_, s2_, s3_;
                { const float2 a = unpk(acc[g][0]); s0_ = a.x + a.y; }
                { const float2 a = unpk(acc[g][1]); s1_ = a.x + a.y; }
                { const float2 a = unpk(acc[g][2]); s2_ = a.x + a.y; }
                { const float2 a = unpk(acc[g][3]); s3_ = a.x + a.y; }
                const float payA = kb ? s0_ : s1_;
                const float rcA  = __shfl_xor_sync(0xffffffffu, payA, 1);
                s0_ += kb ? 0.0f : rcA;
                s1_ += kb ? rcA : 0.0f;
                const float payB = kb ? s2_ : s3_;
                const float rcB  = __shfl_xor_sync(0xffffffffu, payB, 1);
                s2_ += kb ? 0.0f : rcB;
                s3_ += kb ? rcB : 0.0f;
                const float own = kt ? (kb ? s3_ : s2_) : (kb ? s1_ : s0_);
                const float pay = kt ? (kb ? s1_ : s0_) : (kb ? s3_ : s2_);
                gv[g] = own + __shfl_xor_sync(0xffffffffu, pay, 2) + bias[g];
            }
            // activation for row q (always valid, rows 0..3)
            const float cn = sig_(gv[1]) * c0 + sig_(gv[0]) * tanh_(gv[2]);
            c0 = cn;
            hn[q * HXROW + j] = sig_(gv[3]) * tanh_(cn);
        }

        // ================= PASS 2: rows 4..6 =================
        {
            u64 acc[4][3];
#pragma unroll
            for (int g = 0; g < 4; ++g)
#pragma unroll
                for (int r = 0; r < 3; ++r) acc[g][r] = 0ull;

#pragma unroll
            for (int cc = 0; cc < 3; ++cc) {
#pragma unroll
                for (int r = 0; r < 3; ++r) {
                    const ulonglong2 hv =
                        *(const ulonglong2*)&hb[(4 + r) * HXROW + 4 * cc];
#pragma unroll
                    for (int g = 0; g < 4; ++g) {
                        ffma2(acc[g][r], wr[g][2 * cc],     hv.x);
                        ffma2(acc[g][r], wr[g][2 * cc + 1], hv.y);
                    }
                }
            }
#pragma unroll
            for (int m = 0; m < 6; ++m) {
                const u64* bp = Wu + (2 * m) * 2048 + wbase;
                const ulonglong2 w0A = *(const ulonglong2*)(bp + h0off);
                const ulonglong2 w0B = *(const ulonglong2*)(bp + h1off);
                const ulonglong2 w1A = *(const ulonglong2*)(bp + 2048 + h0off);
                const ulonglong2 w1B = *(const ulonglong2*)(bp + 2048 + h1off);
#pragma unroll
                for (int r = 0; r < 3; ++r) {
                    const ulonglong2 hv =
                        *(const ulonglong2*)&hb[(4 + r) * HXROW + 12 + 4 * m];
                    ffma2(acc[0][r], w0A.x, hv.x);
                    ffma2(acc[1][r], w0A.y, hv.x);
                    ffma2(acc[2][r], w0B.x, hv.x);
                    ffma2(acc[3][r], w0B.y, hv.x);
                    ffma2(acc[0][r], w1A.x, hv.y);
                    ffma2(acc[1][r], w1A.y, hv.y);
                    ffma2(acc[2][r], w1B.x, hv.y);
                    ffma2(acc[3][r], w1B.y, hv.y);
                }
            }

            // reduce (rows 4..6) -> thread q owns row q+4 (q<3)
            float gv[4];
#pragma unroll
            for (int g = 0; g < 4; ++g) {
                float s4_, s5_, s6_;
                { const float2 a = unpk(acc[g][0]); s4_ = a.x + a.y; }
                { const float2 a = unpk(acc[g][1]); s5_ = a.x + a.y; }
                { const float2 a = unpk(acc[g][2]); s6_ = a.x + a.y; }
                const float payA = kb ? s4_ : s5_;
                const float rcA  = __shfl_xor_sync(0xffffffffu, payA, 1);
                s4_ += kb ? 0.0f : rcA;
                s5_ += kb ? rcA : 0.0f;
                const float rcB  = __shfl_xor_sync(0xffffffffu, s6_, 1);
                s6_ += kb ? 0.0f : rcB;
                // own: q=0->s4, q=1->s5, q=2->s6, q=3->unused
                const float own = kt ? (kb ? 0.0f : s6_) : (kb ? s5_ : s4_);
                // payload: partner q^2 owns row (q^2)+4:
                // q=0 sends s6 (to q=2), q=2 sends s4 (to q=0),
                // q=3 sends s5 (to q=1), q=1 sends dummy (to q=3)
                const float pay = kt ? (kb ? s5_ : s4_) : s6_;
                gv[g] = own + __shfl_xor_sync(0xffffffffu, pay, 2) + bias[g];
            }
            if (q < 3) {
                const float cn = sig_(gv[1]) * c1 + sig_(gv[0]) * tanh_(gv[2]);
                c1 = cn;
                hn[(q + 4) * HXROW + j] = sig_(gv[3]) * tanh_(cn);
            }
        }

        if (doX)
            hn[xb * HXROW + 128 + xi] = xv;

        __syncthreads();
        cur ^= 1;
    }

    // ---- output: out[b] = h_T[b] . fc_w + fc_b ----
    if (tid < BB && bbase + tid < BTOT) {
        const float* hbf = hx + cur * HXBUF + tid * HXROW;
        float s = fc_b[0];
#pragma unroll 8
        for (int k = 0; k < 128; ++k) s += hbf[k] * fcw[k];
        out[bbase + tid] = s;
    }
}

extern "C" void kernel_launch(void* const* d_in, const int* in_sizes, int n_in,
                              void* d_out, int out_size)
{
    const float* x    = (const float*)d_in[0];
    const float* W_ih = (const float*)d_in[1];
    const float* W_hh = (const float*)d_in[2];
    const float* b_ih = (const float*)d_in[3];
    const float* b_hh = (const float*)d_in[4];
    const float* fc_w = (const float*)d_in[5];
    const float* fc_b = (const float*)d_in[6];
    float* out = (float*)d_out;

    cudaFuncSetAttribute(slstm_kernel,
                         cudaFuncAttributeMaxDynamicSharedMemorySize, SMEM_BYTES);
    slstm_kernel<<<NCTA, NT, SMEM_BYTES>>>(x, W_ih, W_hh, b_ih, b_hh,
                                           fc_w, fc_b, out);
}